// round 9
// baseline (speedup 1.0000x reference)
#include <cuda_runtime.h>
#include <cuda_bf16.h>

#define MAXN 8192
__device__ float4 g_pt[MAXN];   // x, y, ell, theta/tau per point

#define TPB 128
#define ILP 4            // i-lanes per thread = 2 packed f32x2 pairs
#define NPK (ILP / 2)
#define JT  32

typedef unsigned long long u64;

#define ADDX2(o,a,b)   asm("add.rn.f32x2 %0,%1,%2;"    : "=l"(o) : "l"(a), "l"(b))
#define MULX2(o,a,b)   asm("mul.rn.f32x2 %0,%1,%2;"    : "=l"(o) : "l"(a), "l"(b))
#define FMAX2(o,a,b,c) asm("fma.rn.f32x2 %0,%1,%2,%3;" : "=l"(o) : "l"(a), "l"(b), "l"(c))

union f2u { float2 f; u64 u; };

__device__ __forceinline__ u64 dup2f(float v) {
    return (u64)__float_as_uint(v) * 0x100000001ull;
}
__device__ __forceinline__ u64 pk2(float lo, float hi) {
    f2u t; t.f.x = lo; t.f.y = hi; return t.u;
}

__global__ void precompute_xy(const float* __restrict__ ell,
                              const float* __restrict__ theta,
                              float* __restrict__ out, int N) {
    const float INV_TAU = 0.15915494309189533577f;
    int i = blockIdx.x * blockDim.x + threadIdx.x;
    if (i < N) {
        float e = ell[i];
        float t = theta[i];
        float r = expf(e);
        float sn, cs;
        sincosf(t, &sn, &cs);
        float ax = r * (fabsf(cs) + 1e-10f);
        float ay = r * (fabsf(sn) + 1e-10f);
        float4 p;
        p.x = (cs >= 0.f) ? ax : -ax;
        p.y = (sn >= 0.f) ? ay : -ay;
        p.z = e;
        p.w = t * INV_TAU;                 // normalized theta (turns)
        g_pt[i] = p;
        out[i]     = 0.f;                  // fused output zeroing
        out[N + i] = 0.f;
    }
}

__global__ void __launch_bounds__(TPB)
force_kernel(const float* __restrict__ s, const unsigned char* __restrict__ frozen,
             float* __restrict__ out, int N)
{
    // j-tile: {dup(x),dup(y)} and {dup(ell),dup(tn)} as 128-bit rows + dup(s)
    __shared__ ulonglong2 sXY[JT];
    __shared__ ulonglong2 sLT[JT];
    __shared__ u64        sS[JT];

    const float CUT2  = 6.854101966249685f;      // phi^4
    const float TAU_F = 6.28318530717958647692f;

    int tid = threadIdx.x;
    int ibase = blockIdx.x * (TPB * ILP) + tid;

    // ---- prefetch i-data first (overlap LDG latency with j-tile fill) ----
    float4 qi[NPK][2];
#pragma unroll
    for (int p = 0; p < NPK; p++)
#pragma unroll
        for (int h = 0; h < 2; h++) {
            int i = ibase + (2 * p + h) * TPB;
            qi[p][h] = (i < N) ? g_pt[i] : make_float4(1e30f, 1e30f, 0.f, 0.f);
        }

    // ---- j tile ----
    if (tid < JT) {
        int j = blockIdx.y * JT + tid;
        float x = 1e30f, y = 1e30f, l = 0.f, t = 0.f, sv = 0.f;
        if (j < N) {
            float4 p = g_pt[j];
            x = p.x; y = p.y; l = p.z; t = p.w; sv = s[j];
        }
        ulonglong2 a; a.x = dup2f(x); a.y = dup2f(y);
        ulonglong2 b; b.x = dup2f(l); b.y = dup2f(t);
        sXY[tid] = a;
        sLT[tid] = b;
        sS[tid]  = dup2f(sv);
    }

    u64 nx[NPK], ny[NPK], nl[NPK], nt[NPK], fl[NPK], ft[NPK];
#pragma unroll
    for (int p = 0; p < NPK; p++) {
        nx[p] = pk2(-qi[p][0].x, -qi[p][1].x);
        ny[p] = pk2(-qi[p][0].y, -qi[p][1].y);
        nl[p] = pk2(-qi[p][0].z, -qi[p][1].z);
        nt[p] = pk2(-qi[p][0].w, -qi[p][1].w);
        fl[p] = 0ull;
        ft[p] = 0ull;
    }

    __syncthreads();

    const u64 EPS2  = dup2f(1e-30f);
    const u64 NEG1  = dup2f(-1.0f);
    const u64 MAG2  = dup2f(12582912.0f);    //  1.5*2^23
    const u64 NMAG2 = dup2f(-12582912.0f);

#pragma unroll 8
    for (int jj = 0; jj < JT; jj++) {
        ulonglong2 XY = sXY[jj];             // LDS.128
        ulonglong2 LT = sLT[jj];             // LDS.128
        u64        Sj = sS[jj];              // LDS.64
#pragma unroll
        for (int p = 0; p < NPK; p++) {
            u64 dx, dy, t0, d2, r, f, dl, u, t1, w, dthn;
            ADDX2(dx, XY.x, nx[p]);
            ADDX2(dy, XY.y, ny[p]);
            FMAX2(t0, dy, dy, EPS2);         // +1e-30: diagonal finite; dl==dthn==0 there
            FMAX2(d2, dx, dx, t0);
            f2u d2u; d2u.u = d2;
            float rlo = (d2u.f.x <= CUT2) ? rsqrtf(d2u.f.x) : 0.f;
            float rhi = (d2u.f.y <= CUT2) ? rsqrtf(d2u.f.y) : 0.f;
            r = pk2(rlo, rhi);
            MULX2(f, r, Sj);
            ADDX2(dl, LT.x, nl[p]);
            ADDX2(u,  LT.y, nt[p]);          // (tn_j - tn_i), in (-1,1)
            ADDX2(t1, u, MAG2);              // magic rint: (u+M)-M == rint(u)
            ADDX2(w,  t1, NMAG2);
            FMAX2(dthn, w, NEG1, u);         // u - rint(u): wrapped dtheta in turns
            FMAX2(fl[p], f, dl, fl[p]);
            FMAX2(ft[p], f, dthn, ft[p]);
        }
    }

#pragma unroll
    for (int p = 0; p < NPK; p++) {
        f2u a; a.u = fl[p];
        f2u b; b.u = ft[p];
        float fls[2] = {a.f.x, a.f.y};
        float fts[2] = {b.f.x, b.f.y};
#pragma unroll
        for (int h = 0; h < 2; h++) {
            int i = ibase + (2 * p + h) * TPB;
            if (i < N) {
                float m = frozen[i] ? 0.f : s[i];
                atomicAdd(&out[i],     m * fls[h]);
                atomicAdd(&out[N + i], (m * TAU_F) * fts[h]);  // turns -> radians
            }
        }
    }
}

extern "C" void kernel_launch(void* const* d_in, const int* in_sizes, int n_in,
                              void* d_out, int out_size) {
    const float*         ell    = (const float*)d_in[0];
    const float*         theta  = (const float*)d_in[1];
    const float*         s      = (const float*)d_in[2];
    const unsigned char* frozen = (const unsigned char*)d_in[3];
    float* out = (float*)d_out;
    int N = in_sizes[0];

    precompute_xy<<<(N + 255) / 256, 256>>>(ell, theta, out, N);

    dim3 grid((N + TPB * ILP - 1) / (TPB * ILP), (N + JT - 1) / JT);
    force_kernel<<<grid, TPB>>>(s, frozen, out, N);
}

// round 10
// speedup vs baseline: 1.4314x; 1.4314x over previous
#include <cuda_runtime.h>
#include <cuda_bf16.h>

#define MAXN 8192
__device__ float4 g_pt[MAXN];   // x, y, ell, theta/tau per point

#define TPB 128
#define ILP 4            // i-lanes per thread = 2 packed f32x2 pairs
#define NPK (ILP / 2)
#define JT  32

typedef unsigned long long u64;

#define ADDX2(o,a,b)   asm("add.rn.f32x2 %0,%1,%2;"    : "=l"(o) : "l"(a), "l"(b))
#define MULX2(o,a,b)   asm("mul.rn.f32x2 %0,%1,%2;"    : "=l"(o) : "l"(a), "l"(b))
#define FMAX2(o,a,b,c) asm("fma.rn.f32x2 %0,%1,%2,%3;" : "=l"(o) : "l"(a), "l"(b), "l"(c))
#define UNPK(lo,hi,in) asm("mov.b64 {%0,%1}, %2;" : "=f"(lo), "=f"(hi) : "l"(in))
#define PK(o,lo,hi)    asm("mov.b64 %0, {%1,%2};" : "=l"(o) : "f"(lo), "f"(hi))

__device__ __forceinline__ u64 dup2f(float v) {
    return (u64)__float_as_uint(v) * 0x100000001ull;
}

__global__ void precompute_xy(const float* __restrict__ ell,
                              const float* __restrict__ theta,
                              float* __restrict__ out, int N) {
    const float INV_TAU = 0.15915494309189533577f;
    int i = blockIdx.x * blockDim.x + threadIdx.x;
    if (i < N) {
        float e = ell[i];
        float t = theta[i];
        float r = expf(e);
        float sn, cs;
        sincosf(t, &sn, &cs);
        float ax = r * (fabsf(cs) + 1e-10f);
        float ay = r * (fabsf(sn) + 1e-10f);
        float4 p;
        p.x = (cs >= 0.f) ? ax : -ax;
        p.y = (sn >= 0.f) ? ay : -ay;
        p.z = e;
        p.w = t * INV_TAU;                 // normalized theta (turns)
        g_pt[i] = p;
        out[i]     = 0.f;                  // fused output zeroing
        out[N + i] = 0.f;
    }
}

__global__ void __launch_bounds__(TPB)
force_kernel(const float* __restrict__ s, const unsigned char* __restrict__ frozen,
             float* __restrict__ out, int N)
{
    // j-tile: {dup(x),dup(y)} and {dup(ell),dup(tn)} as 128-bit rows + dup(s)
    __shared__ ulonglong2 sXY[JT];
    __shared__ ulonglong2 sLT[JT];
    __shared__ u64        sS[JT];

    const float CUT2  = 6.854101966249685f;      // phi^4
    const float TAU_F = 6.28318530717958647692f;

    int tid = threadIdx.x;
    int ibase = blockIdx.x * (TPB * ILP) + tid;

    // ---- prefetch i-data first (overlap LDG latency with j-tile fill) ----
    float4 qi[NPK][2];
#pragma unroll
    for (int p = 0; p < NPK; p++)
#pragma unroll
        for (int h = 0; h < 2; h++) {
            int i = ibase + (2 * p + h) * TPB;
            qi[p][h] = (i < N) ? g_pt[i] : make_float4(1e30f, 1e30f, 0.f, 0.f);
        }

    // ---- j tile ----
    if (tid < JT) {
        int j = blockIdx.y * JT + tid;
        float x = 1e30f, y = 1e30f, l = 0.f, t = 0.f, sv = 0.f;
        if (j < N) {
            float4 p = g_pt[j];
            x = p.x; y = p.y; l = p.z; t = p.w; sv = s[j];
        }
        ulonglong2 a; a.x = dup2f(x); a.y = dup2f(y);
        ulonglong2 b; b.x = dup2f(l); b.y = dup2f(t);
        sXY[tid] = a;
        sLT[tid] = b;
        sS[tid]  = dup2f(sv);
    }

    u64 nx[NPK], ny[NPK], nl[NPK], nt[NPK], fl[NPK], ft[NPK];
#pragma unroll
    for (int p = 0; p < NPK; p++) {
        PK(nx[p], -qi[p][0].x, -qi[p][1].x);
        PK(ny[p], -qi[p][0].y, -qi[p][1].y);
        PK(nl[p], -qi[p][0].z, -qi[p][1].z);
        PK(nt[p], -qi[p][0].w, -qi[p][1].w);
        fl[p] = 0ull;
        ft[p] = 0ull;
    }

    __syncthreads();

    const u64 EPS2  = dup2f(1e-30f);
    const u64 NEG1  = dup2f(-1.0f);
    const u64 MAG2  = dup2f(12582912.0f);    //  1.5*2^23
    const u64 NMAG2 = dup2f(-12582912.0f);

#pragma unroll 8
    for (int jj = 0; jj < JT; jj++) {
        ulonglong2 XY = sXY[jj];             // LDS.128
        ulonglong2 LT = sLT[jj];             // LDS.128
        u64        Sj = sS[jj];              // LDS.64
#pragma unroll
        for (int p = 0; p < NPK; p++) {
            u64 dx, dy, t0, d2, r, f, dl, u, t1, w, dthn;
            ADDX2(dx, XY.x, nx[p]);
            ADDX2(dy, XY.y, ny[p]);
            FMAX2(t0, dy, dy, EPS2);         // +1e-30: diagonal finite; dl==dthn==0 there
            FMAX2(d2, dx, dx, t0);
            float d2lo, d2hi;
            UNPK(d2lo, d2hi, d2);
            float rlo = (d2lo <= CUT2) ? rsqrtf(d2lo) : 0.f;
            float rhi = (d2hi <= CUT2) ? rsqrtf(d2hi) : 0.f;
            PK(r, rlo, rhi);
            MULX2(f, r, Sj);
            ADDX2(dl, LT.x, nl[p]);
            ADDX2(u,  LT.y, nt[p]);          // (tn_j - tn_i), in (-1,1)
            ADDX2(t1, u, MAG2);              // magic rint: (u+M)-M == rint(u), packed
            ADDX2(w,  t1, NMAG2);
            FMAX2(dthn, w, NEG1, u);         // u - rint(u): wrapped dtheta in turns
            FMAX2(fl[p], f, dl, fl[p]);
            FMAX2(ft[p], f, dthn, ft[p]);
        }
    }

#pragma unroll
    for (int p = 0; p < NPK; p++) {
        float flo, fhi, tlo, thi;
        UNPK(flo, fhi, fl[p]);
        UNPK(tlo, thi, ft[p]);
        float fls[2] = {flo, fhi};
        float fts[2] = {tlo, thi};
#pragma unroll
        for (int h = 0; h < 2; h++) {
            int i = ibase + (2 * p + h) * TPB;
            if (i < N) {
                float m = frozen[i] ? 0.f : s[i];
                atomicAdd(&out[i],     m * fls[h]);
                atomicAdd(&out[N + i], (m * TAU_F) * fts[h]);  // turns -> radians
            }
        }
    }
}

extern "C" void kernel_launch(void* const* d_in, const int* in_sizes, int n_in,
                              void* d_out, int out_size) {
    const float*         ell    = (const float*)d_in[0];
    const float*         theta  = (const float*)d_in[1];
    const float*         s      = (const float*)d_in[2];
    const unsigned char* frozen = (const unsigned char*)d_in[3];
    float* out = (float*)d_out;
    int N = in_sizes[0];

    precompute_xy<<<(N + 255) / 256, 256>>>(ell, theta, out, N);

    dim3 grid((N + TPB * ILP - 1) / (TPB * ILP), (N + JT - 1) / JT);
    force_kernel<<<grid, TPB>>>(s, frozen, out, N);
}

// round 11
// speedup vs baseline: 1.4459x; 1.0101x over previous
#include <cuda_runtime.h>
#include <cuda_bf16.h>

#define MAXN 8192
__device__ float4 g_pt[MAXN];   // x, y, ell, theta/tau per point

#define TPB 128
#define ILP 2            // i-lanes per thread = 1 packed f32x2 pair
#define JT  32

typedef unsigned long long u64;

#define ADDX2(o,a,b)   asm("add.rn.f32x2 %0,%1,%2;"    : "=l"(o) : "l"(a), "l"(b))
#define MULX2(o,a,b)   asm("mul.rn.f32x2 %0,%1,%2;"    : "=l"(o) : "l"(a), "l"(b))
#define FMAX2(o,a,b,c) asm("fma.rn.f32x2 %0,%1,%2,%3;" : "=l"(o) : "l"(a), "l"(b), "l"(c))
#define UNPK(lo,hi,in) asm("mov.b64 {%0,%1}, %2;" : "=f"(lo), "=f"(hi) : "l"(in))
#define PK(o,lo,hi)    asm("mov.b64 %0, {%1,%2};" : "=l"(o) : "f"(lo), "f"(hi))

__device__ __forceinline__ u64 dup2f(float v) {
    return (u64)__float_as_uint(v) * 0x100000001ull;
}

__global__ void precompute_xy(const float* __restrict__ ell,
                              const float* __restrict__ theta,
                              float* __restrict__ out, int N) {
    const float INV_TAU = 0.15915494309189533577f;
    int i = blockIdx.x * blockDim.x + threadIdx.x;
    if (i < N) {
        float e = ell[i];
        float t = theta[i];
        float r = expf(e);
        float sn, cs;
        sincosf(t, &sn, &cs);
        float ax = r * (fabsf(cs) + 1e-10f);
        float ay = r * (fabsf(sn) + 1e-10f);
        float4 p;
        p.x = (cs >= 0.f) ? ax : -ax;
        p.y = (sn >= 0.f) ? ay : -ay;
        p.z = e;
        p.w = t * INV_TAU;                 // normalized theta (turns)
        g_pt[i] = p;
        out[i]     = 0.f;                  // fused output zeroing
        out[N + i] = 0.f;
    }
}

__global__ void __launch_bounds__(TPB)
force_kernel(const float* __restrict__ s, const unsigned char* __restrict__ frozen,
             float* __restrict__ out, int N)
{
    // j-tile: {dup(x),dup(y)} and {dup(ell),dup(tn)} as 128-bit rows + dup(s)
    __shared__ ulonglong2 sXY[JT];
    __shared__ ulonglong2 sLT[JT];
    __shared__ u64        sS[JT];

    const float CUT2  = 6.854101966249685f;      // phi^4
    const float TAU_F = 6.28318530717958647692f;

    int tid = threadIdx.x;
    int ibase = blockIdx.x * (TPB * ILP) + tid;

    // ---- prefetch i-data first (overlap LDG latency with j-tile fill) ----
    float4 qi[2];
#pragma unroll
    for (int h = 0; h < 2; h++) {
        int i = ibase + h * TPB;
        qi[h] = (i < N) ? g_pt[i] : make_float4(1e30f, 1e30f, 0.f, 0.f);
    }

    // ---- j tile ----
    if (tid < JT) {
        int j = blockIdx.y * JT + tid;
        float x = 1e30f, y = 1e30f, l = 0.f, t = 0.f, sv = 0.f;
        if (j < N) {
            float4 p = g_pt[j];
            x = p.x; y = p.y; l = p.z; t = p.w; sv = s[j];
        }
        ulonglong2 a; a.x = dup2f(x); a.y = dup2f(y);
        ulonglong2 b; b.x = dup2f(l); b.y = dup2f(t);
        sXY[tid] = a;
        sLT[tid] = b;
        sS[tid]  = dup2f(sv);
    }

    u64 nx, ny, nl, nt, fl, ft;
    PK(nx, -qi[0].x, -qi[1].x);
    PK(ny, -qi[0].y, -qi[1].y);
    PK(nl, -qi[0].z, -qi[1].z);
    PK(nt, -qi[0].w, -qi[1].w);
    fl = 0ull;
    ft = 0ull;

    __syncthreads();

    const u64 EPS2  = dup2f(1e-30f);
    const u64 NEG1  = dup2f(-1.0f);
    const u64 MAG2  = dup2f(12582912.0f);    //  1.5*2^23
    const u64 NMAG2 = dup2f(-12582912.0f);

#pragma unroll 8
    for (int jj = 0; jj < JT; jj++) {
        ulonglong2 XY = sXY[jj];             // LDS.128
        ulonglong2 LT = sLT[jj];             // LDS.128
        u64        Sj = sS[jj];              // LDS.64
        u64 dx, dy, t0, d2, r, f, dl, u, t1, w, dthn;
        ADDX2(dx, XY.x, nx);
        ADDX2(dy, XY.y, ny);
        FMAX2(t0, dy, dy, EPS2);             // +1e-30: diagonal finite; dl==dthn==0 there
        FMAX2(d2, dx, dx, t0);
        float d2lo, d2hi;
        UNPK(d2lo, d2hi, d2);
        float rlo = (d2lo <= CUT2) ? rsqrtf(d2lo) : 0.f;
        float rhi = (d2hi <= CUT2) ? rsqrtf(d2hi) : 0.f;
        PK(r, rlo, rhi);
        MULX2(f, r, Sj);
        ADDX2(dl, LT.x, nl);
        ADDX2(u,  LT.y, nt);                 // (tn_j - tn_i), in (-1,1)
        ADDX2(t1, u, MAG2);                  // magic rint: (u+M)-M == rint(u), packed
        ADDX2(w,  t1, NMAG2);
        FMAX2(dthn, w, NEG1, u);             // u - rint(u): wrapped dtheta in turns
        FMAX2(fl, f, dl, fl);
        FMAX2(ft, f, dthn, ft);
    }

    {
        float flo, fhi, tlo, thi;
        UNPK(flo, fhi, fl);
        UNPK(tlo, thi, ft);
        float fls[2] = {flo, fhi};
        float fts[2] = {tlo, thi};
#pragma unroll
        for (int h = 0; h < 2; h++) {
            int i = ibase + h * TPB;
            if (i < N) {
                float m = frozen[i] ? 0.f : s[i];
                atomicAdd(&out[i],     m * fls[h]);
                atomicAdd(&out[N + i], (m * TAU_F) * fts[h]);  // turns -> radians
            }
        }
    }
}

extern "C" void kernel_launch(void* const* d_in, const int* in_sizes, int n_in,
                              void* d_out, int out_size) {
    const float*         ell    = (const float*)d_in[0];
    const float*         theta  = (const float*)d_in[1];
    const float*         s      = (const float*)d_in[2];
    const unsigned char* frozen = (const unsigned char*)d_in[3];
    float* out = (float*)d_out;
    int N = in_sizes[0];

    precompute_xy<<<(N + 255) / 256, 256>>>(ell, theta, out, N);

    dim3 grid((N + TPB * ILP - 1) / (TPB * ILP), (N + JT - 1) / JT);
    force_kernel<<<grid, TPB>>>(s, frozen, out, N);
}